// round 1
// baseline (speedup 1.0000x reference)
#include <cuda_runtime.h>
#include <cstdint>

// Problem constants (fixed by reference setup_inputs)
#define BB 16
#define CC 64
#define HH 512
#define WW 512
#define OH (HH / 2)
#define OW (WW / 2)
#define NPLANE (BB * CC)   // 1024 planes

// One block per (plane, output-row). 128 threads.
// Stage the two needed input rows in smem via aligned float4 loads
// (avoids the misaligned-sector waste from the per-plane p_w shift),
// then each thread computes 2 output pixels and writes a float2.
__global__ __launch_bounds__(128)
void EquivariantSubsample_kernel(const float* __restrict__ img,
                                 const int*   __restrict__ p_w,
                                 const int*   __restrict__ p_h,
                                 float*       __restrict__ out) {
    const int bidx  = blockIdx.x;
    const int oy    = bidx & (OH - 1);   // OH = 256
    const int plane = bidx >> 8;

    __shared__ float row0[WW];
    __shared__ float row1[WW];

    const int t  = threadIdx.x;          // 0..127
    const int ph = p_h[plane];
    const int pw = p_w[plane];

    int ys = 2 * oy + ph;
    if (ys > HH - 2) ys = HH - 2;        // clamp (only last row when ph==1)

    const float* base = img + (size_t)plane * (HH * WW);
    const float4* r0g = (const float4*)(base + (size_t)ys * WW);
    const float4* r1g = (const float4*)(base + (size_t)(ys + 1) * WW);

    // 512 floats per row = 128 float4 -> one float4 per thread per row
    ((float4*)row0)[t] = r0g[t];
    ((float4*)row1)[t] = r1g[t];
    __syncthreads();

    float2 res;
    #pragma unroll
    for (int k = 0; k < 2; k++) {
        const int ox = 2 * t + k;
        int xs = 2 * ox + pw;
        if (xs > WW - 2) xs = WW - 2;    // clamp (only last col when pw==1)
        const float m = fmaxf(fmaxf(row0[xs], row0[xs + 1]),
                              fmaxf(row1[xs], row1[xs + 1]));
        (&res.x)[k] = m;
    }

    float2* orow = (float2*)(out + (size_t)plane * (OH * OW) + (size_t)oy * OW);
    orow[t] = res;
}

extern "C" void kernel_launch(void* const* d_in, const int* in_sizes, int n_in,
                              void* d_out, int out_size) {
    const float* images = (const float*)d_in[0];
    const int*   pw     = (const int*)d_in[1];
    const int*   ph     = (const int*)d_in[2];
    float*       out    = (float*)d_out;

    const int nblocks = NPLANE * OH;     // 262144
    EquivariantSubsample_kernel<<<nblocks, 128>>>(images, pw, ph, out);
}

// round 2
// speedup vs baseline: 1.2872x; 1.2872x over previous
#include <cuda_runtime.h>
#include <cstdint>

// Problem constants (fixed by reference setup_inputs)
#define BB 16
#define CC 64
#define HH 512
#define WW 512
#define OH (HH / 2)
#define OW (WW / 2)
#define NPLANE (BB * CC)        // 1024 planes
#define WARPS_PER_BLOCK 8       // 8 output rows per block

// One WARP per (plane, output-row). Each lane owns 16 consecutive input
// columns: 4x LDG.128 per input row, 2 rows -> 8 independent vector loads
// (MLP=8, fully coalesced). Vertical max in registers, then horizontal 2:1
// max. The p_w==1 cross-lane boundary element comes from one shfl_down of
// the vertically-maxed value; lane 31's boundary is exactly the reference's
// clamp (xs = 511 -> 510) and stays in-register. No smem, no barriers.
__global__ __launch_bounds__(32 * WARPS_PER_BLOCK)
void EquivariantSubsample_kernel(const float* __restrict__ img,
                                 const int*   __restrict__ p_w,
                                 const int*   __restrict__ p_h,
                                 float*       __restrict__ out) {
    const int plane  = blockIdx.x >> 5;            // 32 row-groups per plane
    const int rowgrp = blockIdx.x & 31;
    const int warp   = threadIdx.x >> 5;
    const int lane   = threadIdx.x & 31;
    const int oy     = rowgrp * WARPS_PER_BLOCK + warp;   // 0..255

    const int ph = __ldg(p_h + plane);
    const int pw = __ldg(p_w + plane);

    int ys = 2 * oy + ph;
    if (ys > HH - 2) ys = HH - 2;                  // clamp (last row when ph==1)

    const float* r0 = img + (size_t)plane * (HH * WW) + (size_t)ys * WW + lane * 16;
    const float* r1 = r0 + WW;

    // Load 16 floats from each of the two rows, vertical max into m[0..15].
    float m[16];
    #pragma unroll
    for (int j = 0; j < 4; j++) {
        const float4 a = __ldg((const float4*)(r0 + 4 * j));
        const float4 b = __ldg((const float4*)(r1 + 4 * j));
        m[4 * j + 0] = fmaxf(a.x, b.x);
        m[4 * j + 1] = fmaxf(a.y, b.y);
        m[4 * j + 2] = fmaxf(a.z, b.z);
        m[4 * j + 3] = fmaxf(a.w, b.w);
    }

    // Neighbor lane's first element (needed only for pw==1, lanes 0..30).
    const float m16 = __shfl_down_sync(0xffffffffu, m[0], 1);

    float o[8];
    if (pw == 0) {
        #pragma unroll
        for (int k = 0; k < 8; k++)
            o[k] = fmaxf(m[2 * k], m[2 * k + 1]);
    } else {
        #pragma unroll
        for (int k = 0; k < 7; k++)
            o[k] = fmaxf(m[2 * k + 1], m[2 * k + 2]);
        // last pixel of this lane: xs = 16*lane+15, xs+1 crosses to neighbor;
        // global last column (lane 31) clamps xs 511 -> 510.
        o[7] = (lane == 31) ? fmaxf(m[14], m[15]) : fmaxf(m[15], m16);
    }

    float* orow = out + (size_t)plane * (OH * OW) + (size_t)oy * OW + lane * 8;
    ((float4*)orow)[0] = make_float4(o[0], o[1], o[2], o[3]);
    ((float4*)orow)[1] = make_float4(o[4], o[5], o[6], o[7]);
}

extern "C" void kernel_launch(void* const* d_in, const int* in_sizes, int n_in,
                              void* d_out, int out_size) {
    const float* images = (const float*)d_in[0];
    const int*   pw     = (const int*)d_in[1];
    const int*   ph     = (const int*)d_in[2];
    float*       out    = (float*)d_out;

    const int nblocks = NPLANE * (OH / WARPS_PER_BLOCK);   // 1024 * 32 = 32768
    EquivariantSubsample_kernel<<<nblocks, 32 * WARPS_PER_BLOCK>>>(images, pw, ph, out);
}